// round 13
// baseline (speedup 1.0000x reference)
#include <cuda_runtime.h>
#include <cuda_bf16.h>

#define S_LEN 2048
#define B_SZ  16
#define H_DIM 1024

#define N_EBLK 1024          // energy blocks (R8 config)
#define VPS    8             // s-rows per score block

// 8 chunk-partial slabs (race-free -> no init kernel)
__device__ float g_part[8][B_SZ * H_DIM];
__device__ float g_scoresT[B_SZ * S_LEN];   // transposed scores [b][s]
__device__ int   g_done = 0;                // energy-completion counter
                                            // (reset by softmax each run)

// ---------------------------------------------------------------------------
// Fused kernel: blocks [0,1024) = energy partials (R8-proven layout);
// blocks [1024,5120) = score rows. Score blocks PREFETCH their 128 MiB enc
// stream into registers before spin-waiting on g_done, so energy's ~6.5us
// hides entirely under the DRAM stream.
// ---------------------------------------------------------------------------
__global__ void __launch_bounds__(128)
fused_kernel(const float* __restrict__ enc,
             const float* __restrict__ lds,
             const float* __restrict__ W,
             const float* __restrict__ bias)
{
    const int t    = threadIdx.x;
    const int warp = t >> 5;
    const int lane = t & 31;

    if (blockIdx.x < N_EBLK) {
        // ================= energy path (R8) =================
        __shared__ float4 s_st[16 * 32];     // [b][32 float4] (8KB)

        const int rg   = blockIdx.x >> 3;
        const int ch   = blockIdx.x & 7;
        const int row0 = rg * 8 + warp * 2;

        const float4* st4 = reinterpret_cast<const float4*>(lds);  // [B][256]
        const float4* W4  = reinterpret_cast<const float4*>(W);    // [H][256]

        const float4 w0 = W4[(size_t)row0 * 256 + ch * 32 + lane];
        const float4 w1 = W4[(size_t)(row0 + 1) * 256 + ch * 32 + lane];

        #pragma unroll
        for (int i = 0; i < 4; ++i) {
            const int v = t + i * 128;
            const int b = v >> 5;
            const int k = v & 31;
            s_st[v] = st4[b * 256 + ch * 32 + k];
        }
        __syncthreads();

        float a[32];                          // a[r*16+b]
        #pragma unroll
        for (int b = 0; b < 16; ++b) {
            const float4 s = s_st[b * 32 + lane];
            a[b]      = w0.x * s.x + w0.y * s.y + w0.z * s.z + w0.w * s.w;
            a[16 + b] = w1.x * s.x + w1.y * s.y + w1.z * s.z + w1.w * s.w;
        }

        // Value-halving butterfly: lane l ends holding warp-total of a[l].
        int n = 32;
        #pragma unroll
        for (int s = 16; s >= 1; s >>= 1) {
            const int  half = n >> 1;
            const bool up   = (lane & s) != 0;
            #pragma unroll
            for (int i = 0; i < half; ++i) {
                const float send = up ? a[i] : a[i + half];
                const float keep = up ? a[i + half] : a[i];
                a[i] = keep + __shfl_xor_sync(0xFFFFFFFF, send, s);
            }
            n = half;
        }

        const int r = lane >> 4;
        const int b = lane & 15;
        g_part[ch][(size_t)b * H_DIM + row0 + r] = a[0];

        __threadfence();
        __syncthreads();
        if (t == 0)
            atomicAdd(&g_done, 1);
    } else {
        // ================= score path =================
        const int sb = blockIdx.x - N_EBLK;         // 0..4095
        const int b  = sb & (B_SZ - 1);
        const int s0 = (sb >> 4) * VPS;

        const float4* e4 = reinterpret_cast<const float4*>(enc);
        const float4* b4 = reinterpret_cast<const float4*>(bias);

        // Prefetch the full enc tile for this block into registers —
        // these DRAM loads proceed while energy blocks still compute.
        float4 a0[VPS], a1[VPS];
        #pragma unroll
        for (int i = 0; i < VPS; ++i) {
            const size_t row = ((size_t)(s0 + i) * B_SZ + b) * (H_DIM / 4);
            a0[i] = e4[row + t];
            a1[i] = e4[row + 128 + t];
        }

        // Wait for all energy partials.
        if (t == 0) {
            volatile int* p = &g_done;
            while (*p < N_EBLK) __nanosleep(64);
        }
        __syncthreads();

        float4 g0 = b4[t];
        float4 g1 = b4[128 + t];
        #pragma unroll
        for (int c = 0; c < 8; ++c) {
            const float4* p4 = reinterpret_cast<const float4*>(g_part[c]);
            const float4 p0 = p4[b * (H_DIM / 4) + t];
            const float4 p1 = p4[b * (H_DIM / 4) + 128 + t];
            g0.x += p0.x; g0.y += p0.y; g0.z += p0.z; g0.w += p0.w;
            g1.x += p1.x; g1.y += p1.y; g1.z += p1.z; g1.w += p1.w;
        }

        float acc[VPS];
        #pragma unroll
        for (int i = 0; i < VPS; ++i)
            acc[i] = a0[i].x * g0.x + a0[i].y * g0.y
                   + a0[i].z * g0.z + a0[i].w * g0.w
                   + a1[i].x * g1.x + a1[i].y * g1.y
                   + a1[i].z * g1.z + a1[i].w * g1.w;

        #pragma unroll
        for (int i = 0; i < VPS; ++i)
            #pragma unroll
            for (int off = 16; off > 0; off >>= 1)
                acc[i] += __shfl_xor_sync(0xFFFFFFFF, acc[i], off);

        __shared__ float red[4][VPS];
        if (lane == 0) {
            #pragma unroll
            for (int i = 0; i < VPS; ++i)
                red[warp][i] = acc[i];
        }
        __syncthreads();
        if (t < VPS)
            g_scoresT[(size_t)b * S_LEN + s0 + t] =
                red[0][t] + red[1][t] + red[2][t] + red[3][t];
    }
}

// ---------------------------------------------------------------------------
// Softmax: coalesced loads from g_scoresT, block max+sum, scattered stores.
// Also resets g_done for the next graph replay (safe: stream-ordered).
// ---------------------------------------------------------------------------
__global__ void __launch_bounds__(256)
softmax_kernel(float* __restrict__ out)
{
    const int b = blockIdx.x;
    const int t = threadIdx.x;

    const float4* s4 = reinterpret_cast<const float4*>(g_scoresT + (size_t)b * S_LEN);
    float4 v0 = s4[t];
    float4 v1 = s4[t + 256];

    __shared__ float sm[8];
    const int warp = t >> 5, lane = t & 31;

    float mx = fmaxf(fmaxf(fmaxf(v0.x, v0.y), fmaxf(v0.z, v0.w)),
                     fmaxf(fmaxf(v1.x, v1.y), fmaxf(v1.z, v1.w)));
    #pragma unroll
    for (int off = 16; off > 0; off >>= 1)
        mx = fmaxf(mx, __shfl_xor_sync(0xFFFFFFFF, mx, off));
    if (lane == 0) sm[warp] = mx;
    __syncthreads();
    if (warp == 0) {
        float m = (lane < 8) ? sm[lane] : -3.402823466e38f;
        #pragma unroll
        for (int off = 4; off > 0; off >>= 1)
            m = fmaxf(m, __shfl_xor_sync(0xFFFFFFFF, m, off));
        if (lane == 0) sm[0] = m;
    }
    __syncthreads();
    mx = sm[0];
    __syncthreads();

    v0.x = __expf(v0.x - mx); v0.y = __expf(v0.y - mx);
    v0.z = __expf(v0.z - mx); v0.w = __expf(v0.w - mx);
    v1.x = __expf(v1.x - mx); v1.y = __expf(v1.y - mx);
    v1.z = __expf(v1.z - mx); v1.w = __expf(v1.w - mx);

    float sum = v0.x + v0.y + v0.z + v0.w + v1.x + v1.y + v1.z + v1.w;
    #pragma unroll
    for (int off = 16; off > 0; off >>= 1)
        sum += __shfl_xor_sync(0xFFFFFFFF, sum, off);
    if (lane == 0) sm[warp] = sum;
    __syncthreads();
    if (warp == 0) {
        float s = (lane < 8) ? sm[lane] : 0.f;
        #pragma unroll
        for (int off = 4; off > 0; off >>= 1)
            s += __shfl_xor_sync(0xFFFFFFFF, s, off);
        if (lane == 0) sm[0] = s;
    }
    __syncthreads();
    const float inv = 1.0f / sm[0];

    const int sA = t * 4;
    const int sB = 1024 + t * 4;
    out[(size_t)(sA + 0) * B_SZ + b] = v0.x * inv;
    out[(size_t)(sA + 1) * B_SZ + b] = v0.y * inv;
    out[(size_t)(sA + 2) * B_SZ + b] = v0.z * inv;
    out[(size_t)(sA + 3) * B_SZ + b] = v0.w * inv;
    out[(size_t)(sB + 0) * B_SZ + b] = v1.x * inv;
    out[(size_t)(sB + 1) * B_SZ + b] = v1.y * inv;
    out[(size_t)(sB + 2) * B_SZ + b] = v1.z * inv;
    out[(size_t)(sB + 3) * B_SZ + b] = v1.w * inv;

    if (blockIdx.x == 0 && t == 0)
        g_done = 0;                      // re-arm for next graph replay
}

// ---------------------------------------------------------------------------
extern "C" void kernel_launch(void* const* d_in, const int* in_sizes, int n_in,
                              void* d_out, int out_size)
{
    const float* enc  = (const float*)d_in[0];  // [S,B,H]
    const float* lds  = (const float*)d_in[1];  // [2,1,B,H]
    const float* W    = (const float*)d_in[2];  // [H,H]
    const float* bias = (const float*)d_in[3];  // [H]
    float* out = (float*)d_out;                 // [1,1,S,B] == [S,B]

    fused_kernel<<<N_EBLK + (S_LEN / VPS) * B_SZ, 128>>>(enc, lds, W, bias);
    softmax_kernel<<<B_SZ, 256>>>(out);
}